// round 16
// baseline (speedup 1.0000x reference)
#include <cuda_runtime.h>
#include <math.h>

#define NF   128   // num_filters
#define NG   50    // num_gauss
#define HID  128   // hidden
#define TE   64    // edges (or rows) per tile
#define RP   68    // transposed-tile row pad: 272B stride, 16B-aligned rows
#define MAXN 50000
#define MAXE 800000

typedef unsigned long long u64;

// Scratch (no allocation allowed)
__device__ float g_h[MAXN * NF];     // h = x @ lin1^T
__device__ float g_agg[MAXN * NF];   // segment_sum result
__device__ float g_tmp[MAXN * HID];  // ssp(agg @ lin2^T + b)
__device__ float g_w1T[NG * NF];     // w1 transposed [k][f]
__device__ int   g_idx[2 * MAXE];    // normalized int32 edge indices [src | dst]

__device__ __forceinline__ float ssp(float v) {
    return fmaxf(v, 0.0f) + log1pf(expf(-fabsf(v))) - 0.69314718055994531f;
}

// ---- packed fp32x2 helpers (Blackwell FFMA2) --------------------------------
__device__ __forceinline__ u64 splat2(float a) {
    u64 r; asm("mov.b64 %0, {%1, %1};" : "=l"(r) : "f"(a)); return r;
}
__device__ __forceinline__ void fma2(u64& d, u64 a, u64 b) {
    asm("fma.rn.f32x2 %0, %1, %2, %0;" : "+l"(d) : "l"(a), "l"(b));
}
__device__ __forceinline__ float2 unpack2(u64 v) {
    float2 f; asm("mov.b64 {%0, %1}, %2;" : "=f"(f.x), "=f"(f.y) : "l"(v)); return f;
}

// ---------------------------------------------------------------------------
// Fused prep: idx dtype detect+convert, w1 transpose, agg zero (merged)
// ---------------------------------------------------------------------------
__global__ void prep_kernel(const void* __restrict__ ei, const float* __restrict__ w1,
                            float4* __restrict__ agg4, int n4, int E) {
    const int n2e = 2 * E;
    bool is64 = true;
    const unsigned int* w = (const unsigned int*)ei;
#pragma unroll
    for (int j = 1; j < 64; j += 2)
        if (j < n2e) is64 &= (w[j] == 0u);

    int i = blockIdx.x * blockDim.x + threadIdx.x;
    if (i < n2e)
        g_idx[i] = is64 ? (int)((const long long*)ei)[i] : ((const int*)ei)[i];
    if (i < NF * NG) {
        int f = i / NG, k = i - f * NG;
        g_w1T[k * NF + f] = w1[i];
    }
    if (i < n4) agg4[i] = make_float4(0.f, 0.f, 0.f, 0.f);
}

// ---------------------------------------------------------------------------
// Node GEMM v2: out[N,128] = op(A[N,128] @ W^T (+ bias)).
// Uses the PROVEN 23-instr/k broadcast-packed loop from the edge kernel:
// A staged transposed [k][r] (coalesced global reads), row-pairs packed in
// f32x2; W from plain [k][f] smem (lane-spread LDS.128, conflict-free).
// Numerics: each output sums k sequentially in one fma2 lane -> identical.
// smem = 100,352 B -> 2 blocks/SM.
// ---------------------------------------------------------------------------
#define NODE_SMEM ((NF*NF + NF*RP) * 4)

template <bool SSP, bool HASB>
__global__ void __launch_bounds__(256)
node_gemm(const float* __restrict__ A, const float* __restrict__ W,
          const float* __restrict__ bias, float* __restrict__ out, int N)
{
    extern __shared__ float sm[];
    float* wT = sm;            // [k][f] plain, NF*NF
    float* aT = sm + NF * NF;  // [k][r], rows padded to RP

    const int tid = threadIdx.x;
    const int rbase = blockIdx.x * TE;

    // W[f][k] -> wT[k][f] (coalesced reads)
    for (int i = tid; i < NF * NF; i += 256) {
        int f = i >> 7, k = i & (NF - 1);
        wT[k * NF + f] = W[i];
    }
    // A rows -> aT[k][r]; thread i: r = i>>7, k = i&127 (coalesced global reads)
    for (int i = tid; i < TE * NF; i += 256) {
        int r = i >> 7, k = i & (NF - 1);
        int gr = rbase + r;
        aT[k * RP + r] = (gr < N) ? A[(size_t)gr * NF + k] : 0.f;
    }
    __syncthreads();

    const int fg = tid & 31, f0 = fg << 2;
    const int r0 = (tid >> 5) << 3;   // 8 rows per warp (4 packed pairs)

    u64 acc[4][4];
#pragma unroll
    for (int p = 0; p < 4; p++)
#pragma unroll
        for (int j = 0; j < 4; j++) acc[p][j] = 0ULL;

#pragma unroll 4
    for (int k = 0; k < NF; k++) {
        const float4 w4 = *(const float4*)&wT[k * NF + f0];   // lane-spread, conflict-free
        u64 ws0 = splat2(w4.x), ws1 = splat2(w4.y);
        u64 ws2 = splat2(w4.z), ws3 = splat2(w4.w);
        const ulonglong2 a01 = *(const ulonglong2*)&aT[k * RP + r0];      // broadcast
        const ulonglong2 a23 = *(const ulonglong2*)&aT[k * RP + r0 + 4];  // broadcast
        u64 ap0 = a01.x, ap1 = a01.y, ap2 = a23.x, ap3 = a23.y;
        fma2(acc[0][0], ap0, ws0); fma2(acc[0][1], ap0, ws1);
        fma2(acc[0][2], ap0, ws2); fma2(acc[0][3], ap0, ws3);
        fma2(acc[1][0], ap1, ws0); fma2(acc[1][1], ap1, ws1);
        fma2(acc[1][2], ap1, ws2); fma2(acc[1][3], ap1, ws3);
        fma2(acc[2][0], ap2, ws0); fma2(acc[2][1], ap2, ws1);
        fma2(acc[2][2], ap2, ws2); fma2(acc[2][3], ap2, ws3);
        fma2(acc[3][0], ap3, ws0); fma2(acc[3][1], ap3, ws1);
        fma2(acc[3][2], ap3, ws2); fma2(acc[3][3], ap3, ws3);
    }

    float4 bv = make_float4(0.f, 0.f, 0.f, 0.f);
    if (HASB) bv = *(const float4*)(bias + f0);

#pragma unroll
    for (int p = 0; p < 4; p++) {
        float2 t0 = unpack2(acc[p][0]);   // .x = row r0+2p, .y = row r0+2p+1
        float2 t1 = unpack2(acc[p][1]);
        float2 t2 = unpack2(acc[p][2]);
        float2 t3 = unpack2(acc[p][3]);
        int ga = rbase + r0 + 2 * p;
        if (ga < N) {
            float4 v = make_float4(t0.x + bv.x, t1.x + bv.y, t2.x + bv.z, t3.x + bv.w);
            if (SSP) { v.x = ssp(v.x); v.y = ssp(v.y); v.z = ssp(v.z); v.w = ssp(v.w); }
            *(float4*)(out + (size_t)ga * NF + f0) = v;
        }
        int gb = ga + 1;
        if (gb < N) {
            float4 v = make_float4(t0.y + bv.x, t1.y + bv.y, t2.y + bv.z, t3.y + bv.w);
            if (SSP) { v.x = ssp(v.x); v.y = ssp(v.y); v.z = ssp(v.z); v.w = ssp(v.w); }
            *(float4*)(out + (size_t)gb * NF + f0) = v;
        }
    }
}

// ---------------------------------------------------------------------------
// Fused edge kernel — BYTE-IDENTICAL to R15 (best known: 968 us)
// ---------------------------------------------------------------------------
#define EDGE_SMEM_BYTES ((NF*RP + NF*NF + TE) * 4 + 2 * TE * 4)

__global__ void __launch_bounds__(256, 2)
edge_kernel(const float* __restrict__ ea, const float* __restrict__ ew,
            const float* __restrict__ b1,
            const float* __restrict__ w2, const float* __restrict__ b2,
            const float* __restrict__ h, float* __restrict__ agg, int E)
{
    extern __shared__ float sm[];
    float* hT   = sm;                    // NF x RP ([f][e]); rows 0..49 double as eaT[k][e]
    float* w2T  = hT + NF * RP;          // NF*NF  [k][f] plain
    float* sC   = w2T + NF * NF;         // TE
    int*   sSrc = (int*)(sC + TE);       // TE
    int*   sDst = sSrc + TE;             // TE

    const int tid = threadIdx.x;

    for (int i = tid; i < NF * NF; i += 256) {
        int f = i >> 7, k = i & (NF - 1);
        w2T[k * NF + f] = w2[i];
    }

    const int fg = tid & 31, f0 = fg << 2;
    const int e0 = (tid >> 5) << 3;
    const float4 b1v = *(const float4*)(b1 + f0);
    const float4 b2v = *(const float4*)(b2 + f0);

    const int ntiles = (E + TE - 1) / TE;

    float2 pf[7];
    float  pmw = 0.f; int psrc = 0, pdst = 0;
    {
        int nb = blockIdx.x * TE;
#pragma unroll
        for (int j = 0; j < 7; j++) {
            int f2 = tid + j * 256;
            pf[j] = make_float2(0.f, 0.f);
            if (f2 < (TE * NG) / 2) {
                int e = f2 / (NG / 2), kk = (f2 % (NG / 2)) * 2;
                int ge = nb + e;
                if (ge < E) pf[j] = *(const float2*)&ea[(size_t)ge * NG + kk];
            }
        }
        if (tid < TE) {
            int ge = nb + tid;
            if (ge < E) { pmw = ew[ge]; psrc = g_idx[ge]; pdst = g_idx[E + ge]; }
        }
    }

    for (int tile = blockIdx.x; tile < ntiles; tile += gridDim.x) {
        const int ebase = tile * TE;
        __syncthreads();   // A

#pragma unroll
        for (int j = 0; j < 7; j++) {
            int f2 = tid + j * 256;
            if (f2 < (TE * NG) / 2) {
                int e = f2 / (NG / 2), kk = (f2 % (NG / 2)) * 2;
                hT[kk * RP + e]       = pf[j].x;
                hT[(kk + 1) * RP + e] = pf[j].y;
            }
        }
        if (tid < TE) {
            sC[tid]   = 0.5f * (cospif(pmw * 0.1f) + 1.0f);
            sSrc[tid] = psrc;
            sDst[tid] = pdst;
        }

        {
            int nb = (tile + gridDim.x) * TE;
#pragma unroll
            for (int j = 0; j < 7; j++) {
                int f2 = tid + j * 256;
                pf[j] = make_float2(0.f, 0.f);
                if (f2 < (TE * NG) / 2) {
                    int e = f2 / (NG / 2), kk = (f2 % (NG / 2)) * 2;
                    int ge = nb + e;
                    if (ge < E) pf[j] = *(const float2*)&ea[(size_t)ge * NG + kk];
                }
            }
            pmw = 0.f; psrc = 0; pdst = 0;
            if (tid < TE) {
                int ge = nb + tid;
                if (ge < E) { pmw = ew[ge]; psrc = g_idx[ge]; pdst = g_idx[E + ge]; }
            }
        }
        __syncthreads();   // B

        u64 acc[4][4];
#pragma unroll
        for (int p = 0; p < 4; p++)
#pragma unroll
            for (int j = 0; j < 4; j++) acc[p][j] = 0ULL;

#pragma unroll 2
        for (int k = 0; k < NG; k++) {
            const float4 w4 = __ldg((const float4*)&g_w1T[k * NF + f0]);
            u64 ws0 = splat2(w4.x), ws1 = splat2(w4.y);
            u64 ws2 = splat2(w4.z), ws3 = splat2(w4.w);
            const ulonglong2 a01 = *(const ulonglong2*)&hT[k * RP + e0];
            const ulonglong2 a23 = *(const ulonglong2*)&hT[k * RP + e0 + 4];
            u64 ap0 = a01.x, ap1 = a01.y, ap2 = a23.x, ap3 = a23.y;
            fma2(acc[0][0], ap0, ws0); fma2(acc[0][1], ap0, ws1);
            fma2(acc[0][2], ap0, ws2); fma2(acc[0][3], ap0, ws3);
            fma2(acc[1][0], ap1, ws0); fma2(acc[1][1], ap1, ws1);
            fma2(acc[1][2], ap1, ws2); fma2(acc[1][3], ap1, ws3);
            fma2(acc[2][0], ap2, ws0); fma2(acc[2][1], ap2, ws1);
            fma2(acc[2][2], ap2, ws2); fma2(acc[2][3], ap2, ws3);
            fma2(acc[3][0], ap3, ws0); fma2(acc[3][1], ap3, ws1);
            fma2(acc[3][2], ap3, ws2); fma2(acc[3][3], ap3, ws3);
        }
        __syncthreads();   // C

#pragma unroll
        for (int j = 0; j < 4; j++) {
            float bj = (j == 0) ? b1v.x : (j == 1) ? b1v.y : (j == 2) ? b1v.z : b1v.w;
            float2 t0 = unpack2(acc[0][j]);
            float2 t1 = unpack2(acc[1][j]);
            float2 t2 = unpack2(acc[2][j]);
            float2 t3 = unpack2(acc[3][j]);
            float4 v0 = make_float4(ssp(t0.x + bj), ssp(t0.y + bj),
                                    ssp(t1.x + bj), ssp(t1.y + bj));
            float4 v1 = make_float4(ssp(t2.x + bj), ssp(t2.y + bj),
                                    ssp(t3.x + bj), ssp(t3.y + bj));
            *(float4*)&hT[(f0 + j) * RP + e0]     = v0;
            *(float4*)&hT[(f0 + j) * RP + e0 + 4] = v1;
        }
        __syncthreads();   // D

        u64 acc2[4][4];
#pragma unroll
        for (int p = 0; p < 4; p++)
#pragma unroll
            for (int j = 0; j < 4; j++) acc2[p][j] = 0ULL;

#pragma unroll 4
        for (int k = 0; k < NF; k++) {
            const float4 w4 = *(const float4*)&w2T[k * NF + f0];
            u64 ws0 = splat2(w4.x), ws1 = splat2(w4.y);
            u64 ws2 = splat2(w4.z), ws3 = splat2(w4.w);
            const ulonglong2 a01 = *(const ulonglong2*)&hT[k * RP + e0];
            const ulonglong2 a23 = *(const ulonglong2*)&hT[k * RP + e0 + 4];
            u64 ap0 = a01.x, ap1 = a01.y, ap2 = a23.x, ap3 = a23.y;
            fma2(acc2[0][0], ap0, ws0); fma2(acc2[0][1], ap0, ws1);
            fma2(acc2[0][2], ap0, ws2); fma2(acc2[0][3], ap0, ws3);
            fma2(acc2[1][0], ap1, ws0); fma2(acc2[1][1], ap1, ws1);
            fma2(acc2[1][2], ap1, ws2); fma2(acc2[1][3], ap1, ws3);
            fma2(acc2[2][0], ap2, ws0); fma2(acc2[2][1], ap2, ws1);
            fma2(acc2[2][2], ap2, ws2); fma2(acc2[2][3], ap2, ws3);
            fma2(acc2[3][0], ap3, ws0); fma2(acc2[3][1], ap3, ws1);
            fma2(acc2[3][2], ap3, ws2); fma2(acc2[3][3], ap3, ws3);
        }

#pragma unroll
        for (int p = 0; p < 4; p++) {
            float2 t0 = unpack2(acc2[p][0]);
            float2 t1 = unpack2(acc2[p][1]);
            float2 t2 = unpack2(acc2[p][2]);
            float2 t3 = unpack2(acc2[p][3]);
            int ia = e0 + 2 * p, ib = ia + 1;
            float4 hsa = *(const float4*)(h + (size_t)sSrc[ia] * NF + f0);
            float4 hsb = *(const float4*)(h + (size_t)sSrc[ib] * NF + f0);
            if (ebase + ia < E) {
                float ca = sC[ia];
                float4 ma = make_float4((t0.x + b2v.x) * ca * hsa.x,
                                        (t1.x + b2v.y) * ca * hsa.y,
                                        (t2.x + b2v.z) * ca * hsa.z,
                                        (t3.x + b2v.w) * ca * hsa.w);
                atomicAdd((float4*)(agg + (size_t)sDst[ia] * NF + f0), ma);
            }
            if (ebase + ib < E) {
                float cb = sC[ib];
                float4 mb = make_float4((t0.y + b2v.x) * cb * hsb.x,
                                        (t1.y + b2v.y) * cb * hsb.y,
                                        (t2.y + b2v.z) * cb * hsb.z,
                                        (t3.y + b2v.w) * cb * hsb.w);
                atomicAdd((float4*)(agg + (size_t)sDst[ib] * NF + f0), mb);
            }
        }
    }
}

// ---------------------------------------------------------------------------
// launch
// ---------------------------------------------------------------------------
extern "C" void kernel_launch(void* const* d_in, const int* in_sizes, int n_in,
                              void* d_out, int out_size)
{
    const float* x      = (const float*)d_in[0];
    const void*  ei     = d_in[1];
    const float* ew     = (const float*)d_in[2];
    const float* ea     = (const float*)d_in[3];
    const float* mlp_w1 = (const float*)d_in[4];
    const float* mlp_b1 = (const float*)d_in[5];
    const float* mlp_w2 = (const float*)d_in[6];
    const float* mlp_b2 = (const float*)d_in[7];
    const float* lin1_w = (const float*)d_in[8];
    const float* lin2_w = (const float*)d_in[9];
    const float* lin2_b = (const float*)d_in[10];
    const float* lin_w  = (const float*)d_in[11];
    const float* lin_b  = (const float*)d_in[12];

    const int N = in_sizes[0] / HID;
    const int E = in_sizes[1] / 2;

    float *hbuf, *aggbuf, *tmpbuf;
    cudaGetSymbolAddress((void**)&hbuf,   g_h);
    cudaGetSymbolAddress((void**)&aggbuf, g_agg);
    cudaGetSymbolAddress((void**)&tmpbuf, g_tmp);

    cudaFuncSetAttribute(edge_kernel, cudaFuncAttributeMaxDynamicSharedMemorySize, EDGE_SMEM_BYTES);
    cudaFuncSetAttribute(node_gemm<false, false>, cudaFuncAttributeMaxDynamicSharedMemorySize, NODE_SMEM);
    cudaFuncSetAttribute(node_gemm<true,  true >, cudaFuncAttributeMaxDynamicSharedMemorySize, NODE_SMEM);
    cudaFuncSetAttribute(node_gemm<false, true >, cudaFuncAttributeMaxDynamicSharedMemorySize, NODE_SMEM);

    int dev = 0;
    cudaGetDevice(&dev);
    int sms = 148;
    cudaDeviceGetAttribute(&sms, cudaDevAttrMultiProcessorCount, dev);

    // 1. fused prep: idx convert (+dtype detect), w1 transpose, agg zero
    {
        int n4 = (N * NF) / 4;
        int nthr = 2 * E;
        if (NF * NG > nthr) nthr = NF * NG;
        if (n4 > nthr) nthr = n4;
        prep_kernel<<<(nthr + 255) / 256, 256>>>(ei, mlp_w1, (float4*)aggbuf, n4, E);
    }
    // 2. h = x @ lin1^T
    node_gemm<false, false><<<(N + TE - 1) / TE, 256, NODE_SMEM>>>(x, lin1_w, nullptr, hbuf, N);
    // 3. fused edge MLP + gather + scatter (persistent, 2 blocks/SM) [profiled]
    edge_kernel<<<2 * sms, 256, EDGE_SMEM_BYTES>>>(ea, ew, mlp_b1,
                                                   mlp_w2, mlp_b2, hbuf, aggbuf, E);
    // 4. tmp = ssp(agg @ lin2^T + b2)
    node_gemm<true, true><<<(N + TE - 1) / TE, 256, NODE_SMEM>>>(aggbuf, lin2_w, lin2_b, tmpbuf, N);
    // 5. out = tmp @ lin^T + b
    node_gemm<false, true><<<(N + TE - 1) / TE, 256, NODE_SMEM>>>(tmpbuf, lin_w, lin_b, (float*)d_out, N);
}

// round 17
// speedup vs baseline: 1.0359x; 1.0359x over previous
#include <cuda_runtime.h>
#include <math.h>

#define NF   128   // num_filters
#define NG   50    // num_gauss
#define HID  128   // hidden
#define TE   64    // edges (or rows) per tile
#define RP   68    // transposed-tile row pad: 272B stride, 16B-aligned rows
#define MAXN 50000
#define MAXE 800000

typedef unsigned long long u64;

// Scratch (no allocation allowed)
__device__ float g_h[MAXN * NF];     // h = x @ lin1^T
__device__ float g_agg[MAXN * NF];   // segment_sum result
__device__ float g_tmp[MAXN * HID];  // ssp(agg @ lin2^T + b)
__device__ float g_w1T[NG * NF];     // w1 transposed [k][f]
__device__ int   g_idx[2 * MAXE];    // normalized int32 edge indices [src | dst]

__device__ __forceinline__ float ssp(float v) {
    return fmaxf(v, 0.0f) + log1pf(expf(-fabsf(v))) - 0.69314718055994531f;
}

// ---- packed fp32x2 helpers (Blackwell FFMA2) --------------------------------
__device__ __forceinline__ u64 splat2(float a) {
    u64 r; asm("mov.b64 %0, {%1, %1};" : "=l"(r) : "f"(a)); return r;
}
__device__ __forceinline__ void fma2(u64& d, u64 a, u64 b) {
    asm("fma.rn.f32x2 %0, %1, %2, %0;" : "+l"(d) : "l"(a), "l"(b));
}
__device__ __forceinline__ float2 unpack2(u64 v) {
    float2 f; asm("mov.b64 {%0, %1}, %2;" : "=f"(f.x), "=f"(f.y) : "l"(v)); return f;
}

// Swizzled index (node_gemm staging/reads, proven R9)
__device__ __forceinline__ int widx(int k, int fg) {
    return k * NF + (((fg) ^ (k & 31)) << 2);
}

// ---------------------------------------------------------------------------
// Fused prep (kept from R16 — passed): idx dtype detect+convert, w1 transpose,
// agg zero, all in one launch.
// ---------------------------------------------------------------------------
__global__ void prep_kernel(const void* __restrict__ ei, const float* __restrict__ w1,
                            float4* __restrict__ agg4, int n4, int E) {
    const int n2e = 2 * E;
    bool is64 = true;
    const unsigned int* w = (const unsigned int*)ei;
#pragma unroll
    for (int j = 1; j < 64; j += 2)
        if (j < n2e) is64 &= (w[j] == 0u);

    int i = blockIdx.x * blockDim.x + threadIdx.x;
    if (i < n2e)
        g_idx[i] = is64 ? (int)((const long long*)ei)[i] : ((const int*)ei)[i];
    if (i < NF * NG) {
        int f = i / NG, k = i - f * NG;
        g_w1T[k * NF + f] = w1[i];
    }
    if (i < n4) agg4[i] = make_float4(0.f, 0.f, 0.f, 0.f);
}

// ---------------------------------------------------------------------------
// Node GEMM — REVERTED byte-for-byte to proven R9 (60.5 us):
// swizzled wT staging (conflict-free STS), row-major float4 A staging
// (coalesced, conflict-free), splat-per-A inner loop.
// ---------------------------------------------------------------------------
#define NODE_SMEM ((NF*NF + TE*NF) * 4)

template <bool SSP, bool HASB>
__global__ void __launch_bounds__(256)
node_gemm(const float* __restrict__ A, const float* __restrict__ W,
          const float* __restrict__ bias, float* __restrict__ out, int N)
{
    extern __shared__ float sm[];
    float* wT = sm;            // swizzled [k][f]
    float* aN = sm + NF * NF;  // row-major [r][k]

    const int tid = threadIdx.x;
    const int rbase = blockIdx.x * TE;

    for (int i = tid; i < NF * NF; i += 256) {
        int f = i >> 7, k = i & (NF - 1);
        wT[widx(k, f >> 2) + (f & 3)] = W[i];
    }
    {
        const float4 z4 = make_float4(0.f, 0.f, 0.f, 0.f);
        for (int i = tid; i < TE * (NF / 4); i += 256) {
            int r = i >> 5;
            int gr = rbase + r;
            ((float4*)aN)[i] = (gr < N)
                ? ((const float4*)A)[(size_t)gr * (NF / 4) + (i & 31)] : z4;
        }
    }
    __syncthreads();

    const int fg = tid & 31, f0 = fg << 2;
    const int r0 = (tid >> 5) << 3;

    u64 acc[8][2];
#pragma unroll
    for (int i = 0; i < 8; i++) { acc[i][0] = 0ULL; acc[i][1] = 0ULL; }

#pragma unroll 8
    for (int k = 0; k < NF; k++) {
        const ulonglong2 wv = *(const ulonglong2*)&wT[widx(k, fg)];
#pragma unroll
        for (int i = 0; i < 8; i++) {
            u64 aa = splat2(aN[(r0 + i) * NF + k]);
            fma2(acc[i][0], aa, wv.x);
            fma2(acc[i][1], aa, wv.y);
        }
    }

    float4 bv = make_float4(0.f, 0.f, 0.f, 0.f);
    if (HASB) bv = *(const float4*)(bias + f0);

#pragma unroll
    for (int i = 0; i < 8; i++) {
        int gr = rbase + r0 + i;
        if (gr < N) {
            float2 p0 = unpack2(acc[i][0]);
            float2 p1 = unpack2(acc[i][1]);
            float4 v;
            v.x = p0.x + bv.x;
            v.y = p0.y + bv.y;
            v.z = p1.x + bv.z;
            v.w = p1.y + bv.w;
            if (SSP) { v.x = ssp(v.x); v.y = ssp(v.y); v.z = ssp(v.z); v.w = ssp(v.w); }
            *(float4*)(out + (size_t)gr * NF + f0) = v;
        }
    }
}

// ---------------------------------------------------------------------------
// Fused edge kernel — BYTE-IDENTICAL to R15 (best known: 968 us)
// ---------------------------------------------------------------------------
#define EDGE_SMEM_BYTES ((NF*RP + NF*NF + TE) * 4 + 2 * TE * 4)

__global__ void __launch_bounds__(256, 2)
edge_kernel(const float* __restrict__ ea, const float* __restrict__ ew,
            const float* __restrict__ b1,
            const float* __restrict__ w2, const float* __restrict__ b2,
            const float* __restrict__ h, float* __restrict__ agg, int E)
{
    extern __shared__ float sm[];
    float* hT   = sm;                    // NF x RP ([f][e]); rows 0..49 double as eaT[k][e]
    float* w2T  = hT + NF * RP;          // NF*NF  [k][f] plain
    float* sC   = w2T + NF * NF;         // TE
    int*   sSrc = (int*)(sC + TE);       // TE
    int*   sDst = sSrc + TE;             // TE

    const int tid = threadIdx.x;

    for (int i = tid; i < NF * NF; i += 256) {
        int f = i >> 7, k = i & (NF - 1);
        w2T[k * NF + f] = w2[i];
    }

    const int fg = tid & 31, f0 = fg << 2;
    const int e0 = (tid >> 5) << 3;
    const float4 b1v = *(const float4*)(b1 + f0);
    const float4 b2v = *(const float4*)(b2 + f0);

    const int ntiles = (E + TE - 1) / TE;

    float2 pf[7];
    float  pmw = 0.f; int psrc = 0, pdst = 0;
    {
        int nb = blockIdx.x * TE;
#pragma unroll
        for (int j = 0; j < 7; j++) {
            int f2 = tid + j * 256;
            pf[j] = make_float2(0.f, 0.f);
            if (f2 < (TE * NG) / 2) {
                int e = f2 / (NG / 2), kk = (f2 % (NG / 2)) * 2;
                int ge = nb + e;
                if (ge < E) pf[j] = *(const float2*)&ea[(size_t)ge * NG + kk];
            }
        }
        if (tid < TE) {
            int ge = nb + tid;
            if (ge < E) { pmw = ew[ge]; psrc = g_idx[ge]; pdst = g_idx[E + ge]; }
        }
    }

    for (int tile = blockIdx.x; tile < ntiles; tile += gridDim.x) {
        const int ebase = tile * TE;
        __syncthreads();   // A

#pragma unroll
        for (int j = 0; j < 7; j++) {
            int f2 = tid + j * 256;
            if (f2 < (TE * NG) / 2) {
                int e = f2 / (NG / 2), kk = (f2 % (NG / 2)) * 2;
                hT[kk * RP + e]       = pf[j].x;
                hT[(kk + 1) * RP + e] = pf[j].y;
            }
        }
        if (tid < TE) {
            sC[tid]   = 0.5f * (cospif(pmw * 0.1f) + 1.0f);
            sSrc[tid] = psrc;
            sDst[tid] = pdst;
        }

        {
            int nb = (tile + gridDim.x) * TE;
#pragma unroll
            for (int j = 0; j < 7; j++) {
                int f2 = tid + j * 256;
                pf[j] = make_float2(0.f, 0.f);
                if (f2 < (TE * NG) / 2) {
                    int e = f2 / (NG / 2), kk = (f2 % (NG / 2)) * 2;
                    int ge = nb + e;
                    if (ge < E) pf[j] = *(const float2*)&ea[(size_t)ge * NG + kk];
                }
            }
            pmw = 0.f; psrc = 0; pdst = 0;
            if (tid < TE) {
                int ge = nb + tid;
                if (ge < E) { pmw = ew[ge]; psrc = g_idx[ge]; pdst = g_idx[E + ge]; }
            }
        }
        __syncthreads();   // B

        u64 acc[4][4];
#pragma unroll
        for (int p = 0; p < 4; p++)
#pragma unroll
            for (int j = 0; j < 4; j++) acc[p][j] = 0ULL;

#pragma unroll 2
        for (int k = 0; k < NG; k++) {
            const float4 w4 = __ldg((const float4*)&g_w1T[k * NF + f0]);
            u64 ws0 = splat2(w4.x), ws1 = splat2(w4.y);
            u64 ws2 = splat2(w4.z), ws3 = splat2(w4.w);
            const ulonglong2 a01 = *(const ulonglong2*)&hT[k * RP + e0];
            const ulonglong2 a23 = *(const ulonglong2*)&hT[k * RP + e0 + 4];
            u64 ap0 = a01.x, ap1 = a01.y, ap2 = a23.x, ap3 = a23.y;
            fma2(acc[0][0], ap0, ws0); fma2(acc[0][1], ap0, ws1);
            fma2(acc[0][2], ap0, ws2); fma2(acc[0][3], ap0, ws3);
            fma2(acc[1][0], ap1, ws0); fma2(acc[1][1], ap1, ws1);
            fma2(acc[1][2], ap1, ws2); fma2(acc[1][3], ap1, ws3);
            fma2(acc[2][0], ap2, ws0); fma2(acc[2][1], ap2, ws1);
            fma2(acc[2][2], ap2, ws2); fma2(acc[2][3], ap2, ws3);
            fma2(acc[3][0], ap3, ws0); fma2(acc[3][1], ap3, ws1);
            fma2(acc[3][2], ap3, ws2); fma2(acc[3][3], ap3, ws3);
        }
        __syncthreads();   // C

#pragma unroll
        for (int j = 0; j < 4; j++) {
            float bj = (j == 0) ? b1v.x : (j == 1) ? b1v.y : (j == 2) ? b1v.z : b1v.w;
            float2 t0 = unpack2(acc[0][j]);
            float2 t1 = unpack2(acc[1][j]);
            float2 t2 = unpack2(acc[2][j]);
            float2 t3 = unpack2(acc[3][j]);
            float4 v0 = make_float4(ssp(t0.x + bj), ssp(t0.y + bj),
                                    ssp(t1.x + bj), ssp(t1.y + bj));
            float4 v1 = make_float4(ssp(t2.x + bj), ssp(t2.y + bj),
                                    ssp(t3.x + bj), ssp(t3.y + bj));
            *(float4*)&hT[(f0 + j) * RP + e0]     = v0;
            *(float4*)&hT[(f0 + j) * RP + e0 + 4] = v1;
        }
        __syncthreads();   // D

        u64 acc2[4][4];
#pragma unroll
        for (int p = 0; p < 4; p++)
#pragma unroll
            for (int j = 0; j < 4; j++) acc2[p][j] = 0ULL;

#pragma unroll 4
        for (int k = 0; k < NF; k++) {
            const float4 w4 = *(const float4*)&w2T[k * NF + f0];
            u64 ws0 = splat2(w4.x), ws1 = splat2(w4.y);
            u64 ws2 = splat2(w4.z), ws3 = splat2(w4.w);
            const ulonglong2 a01 = *(const ulonglong2*)&hT[k * RP + e0];
            const ulonglong2 a23 = *(const ulonglong2*)&hT[k * RP + e0 + 4];
            u64 ap0 = a01.x, ap1 = a01.y, ap2 = a23.x, ap3 = a23.y;
            fma2(acc2[0][0], ap0, ws0); fma2(acc2[0][1], ap0, ws1);
            fma2(acc2[0][2], ap0, ws2); fma2(acc2[0][3], ap0, ws3);
            fma2(acc2[1][0], ap1, ws0); fma2(acc2[1][1], ap1, ws1);
            fma2(acc2[1][2], ap1, ws2); fma2(acc2[1][3], ap1, ws3);
            fma2(acc2[2][0], ap2, ws0); fma2(acc2[2][1], ap2, ws1);
            fma2(acc2[2][2], ap2, ws2); fma2(acc2[2][3], ap2, ws3);
            fma2(acc2[3][0], ap3, ws0); fma2(acc2[3][1], ap3, ws1);
            fma2(acc2[3][2], ap3, ws2); fma2(acc2[3][3], ap3, ws3);
        }

#pragma unroll
        for (int p = 0; p < 4; p++) {
            float2 t0 = unpack2(acc2[p][0]);
            float2 t1 = unpack2(acc2[p][1]);
            float2 t2 = unpack2(acc2[p][2]);
            float2 t3 = unpack2(acc2[p][3]);
            int ia = e0 + 2 * p, ib = ia + 1;
            float4 hsa = *(const float4*)(h + (size_t)sSrc[ia] * NF + f0);
            float4 hsb = *(const float4*)(h + (size_t)sSrc[ib] * NF + f0);
            if (ebase + ia < E) {
                float ca = sC[ia];
                float4 ma = make_float4((t0.x + b2v.x) * ca * hsa.x,
                                        (t1.x + b2v.y) * ca * hsa.y,
                                        (t2.x + b2v.z) * ca * hsa.z,
                                        (t3.x + b2v.w) * ca * hsa.w);
                atomicAdd((float4*)(agg + (size_t)sDst[ia] * NF + f0), ma);
            }
            if (ebase + ib < E) {
                float cb = sC[ib];
                float4 mb = make_float4((t0.y + b2v.x) * cb * hsb.x,
                                        (t1.y + b2v.y) * cb * hsb.y,
                                        (t2.y + b2v.z) * cb * hsb.z,
                                        (t3.y + b2v.w) * cb * hsb.w);
                atomicAdd((float4*)(agg + (size_t)sDst[ib] * NF + f0), mb);
            }
        }
    }
}

// ---------------------------------------------------------------------------
// launch
// ---------------------------------------------------------------------------
extern "C" void kernel_launch(void* const* d_in, const int* in_sizes, int n_in,
                              void* d_out, int out_size)
{
    const float* x      = (const float*)d_in[0];
    const void*  ei     = d_in[1];
    const float* ew     = (const float*)d_in[2];
    const float* ea     = (const float*)d_in[3];
    const float* mlp_w1 = (const float*)d_in[4];
    const float* mlp_b1 = (const float*)d_in[5];
    const float* mlp_w2 = (const float*)d_in[6];
    const float* mlp_b2 = (const float*)d_in[7];
    const float* lin1_w = (const float*)d_in[8];
    const float* lin2_w = (const float*)d_in[9];
    const float* lin2_b = (const float*)d_in[10];
    const float* lin_w  = (const float*)d_in[11];
    const float* lin_b  = (const float*)d_in[12];

    const int N = in_sizes[0] / HID;
    const int E = in_sizes[1] / 2;

    float *hbuf, *aggbuf, *tmpbuf;
    cudaGetSymbolAddress((void**)&hbuf,   g_h);
    cudaGetSymbolAddress((void**)&aggbuf, g_agg);
    cudaGetSymbolAddress((void**)&tmpbuf, g_tmp);

    cudaFuncSetAttribute(edge_kernel, cudaFuncAttributeMaxDynamicSharedMemorySize, EDGE_SMEM_BYTES);
    cudaFuncSetAttribute(node_gemm<false, false>, cudaFuncAttributeMaxDynamicSharedMemorySize, NODE_SMEM);
    cudaFuncSetAttribute(node_gemm<true,  true >, cudaFuncAttributeMaxDynamicSharedMemorySize, NODE_SMEM);
    cudaFuncSetAttribute(node_gemm<false, true >, cudaFuncAttributeMaxDynamicSharedMemorySize, NODE_SMEM);

    int dev = 0;
    cudaGetDevice(&dev);
    int sms = 148;
    cudaDeviceGetAttribute(&sms, cudaDevAttrMultiProcessorCount, dev);

    // 1. fused prep: idx convert (+dtype detect), w1 transpose, agg zero
    {
        int n4 = (N * NF) / 4;
        int nthr = 2 * E;
        if (NF * NG > nthr) nthr = NF * NG;
        if (n4 > nthr) nthr = n4;
        prep_kernel<<<(nthr + 255) / 256, 256>>>(ei, mlp_w1, (float4*)aggbuf, n4, E);
    }
    // 2. h = x @ lin1^T
    node_gemm<false, false><<<(N + TE - 1) / TE, 256, NODE_SMEM>>>(x, lin1_w, nullptr, hbuf, N);
    // 3. fused edge MLP + gather + scatter (persistent, 2 blocks/SM) [profiled]
    edge_kernel<<<2 * sms, 256, EDGE_SMEM_BYTES>>>(ea, ew, mlp_b1,
                                                   mlp_w2, mlp_b2, hbuf, aggbuf, E);
    // 4. tmp = ssp(agg @ lin2^T + b2)
    node_gemm<true, true><<<(N + TE - 1) / TE, 256, NODE_SMEM>>>(aggbuf, lin2_w, lin2_b, tmpbuf, N);
    // 5. out = tmp @ lin^T + b
    node_gemm<false, true><<<(N + TE - 1) / TE, 256, NODE_SMEM>>>(tmpbuf, lin_w, lin_b, (float*)d_out, N);
}